// round 1
// baseline (speedup 1.0000x reference)
#include <cuda_runtime.h>

#define NG    32
#define NPG   1024
#define NN    32768
#define FDIM  128
#define EMB   32

// output layout (float32 concat of (xe, edge_index_out, edge_weight))
#define OFF_SRC 1048576
#define OFF_DST 34603008
#define OFF_W   68157440

// scratch (static __device__ globals, no allocation)
__device__ __align__(16) float g_xgT[NG * EMB * NPG];  // [g][k][node] transposed
__device__ float g_sq[NN];
__device__ float g_centroid[EMB];
__device__ float g_scale;

// ---------------------------------------------------------------------------
// K1: xe = x @ W   (32768x128 @ 128x32), writes xe into d_out[0..1048576)
// warp-per-row, 4 rows per warp, W transposed in smem for LDS.128
// ---------------------------------------------------------------------------
__global__ void __launch_bounds__(256) k_gemm(const float* __restrict__ x,
                                              const float* __restrict__ W,
                                              float* __restrict__ xe) {
    __shared__ __align__(16) float WsT[32][132];   // [c][k], pad keeps 16B align
    __shared__ __align__(16) float xs[32][128];

    const int t = threadIdx.x;
    for (int i = t; i < FDIM * EMB; i += 256) {
        int k = i >> 5, c = i & 31;
        WsT[c][k] = W[i];
    }
    const int warp = t >> 5, lane = t & 31;
    #pragma unroll
    for (int rr = 0; rr < 4; rr++) {
        int lr = warp * 4 + rr;
        int row = blockIdx.x * 32 + lr;
        float4 v = ((const float4*)(x + (size_t)row * FDIM))[lane];
        *(float4*)&xs[lr][lane * 4] = v;
    }
    __syncthreads();

    #pragma unroll
    for (int rr = 0; rr < 4; rr++) {
        int lr = warp * 4 + rr;
        int row = blockIdx.x * 32 + lr;
        const float4* wv4 = (const float4*)&WsT[lane][0];
        const float4* xv4 = (const float4*)&xs[lr][0];
        float acc = 0.f;
        #pragma unroll
        for (int kq = 0; kq < 32; kq++) {
            float4 wv = wv4[kq];
            float4 xv = xv4[kq];
            acc = fmaf(xv.x, wv.x, acc);
            acc = fmaf(xv.y, wv.y, acc);
            acc = fmaf(xv.z, wv.z, acc);
            acc = fmaf(xv.w, wv.w, acc);
        }
        xe[row * EMB + lane] = acc;
    }
}

// ---------------------------------------------------------------------------
// K2: centroid = mean(xe[:1024], axis=0); scale = 0.9 / max|xe[:1024]-centroid|
// single block, 1024 threads
// ---------------------------------------------------------------------------
__global__ void k_stats(const float* __restrict__ xe) {
    __shared__ float ps[32][33];
    __shared__ float cent[32];
    __shared__ float mx[32];
    const int t = threadIdx.x;           // 1024
    const int col = t & 31, part = t >> 5;
    const int r0 = part * 32;

    float s = 0.f;
    for (int r = r0; r < r0 + 32; r++) s += xe[r * EMB + col];
    ps[part][col] = s;
    __syncthreads();
    if (t < 32) {
        float c = 0.f;
        for (int p = 0; p < 32; p++) c += ps[p][t];
        c *= (1.0f / 1024.0f);
        cent[t] = c;
        g_centroid[t] = c;
    }
    __syncthreads();

    float cc = cent[col];
    float m = 0.f;
    for (int r = r0; r < r0 + 32; r++) m = fmaxf(m, fabsf(xe[r * EMB + col] - cc));
    ps[part][col] = m;
    __syncthreads();
    if (t < 32) {
        float mm = 0.f;
        for (int p = 0; p < 32; p++) mm = fmaxf(mm, ps[p][t]);
        mx[t] = mm;
    }
    __syncthreads();
    if (t == 0) {
        float mm = 0.f;
        for (int c = 0; c < 32; c++) mm = fmaxf(mm, mx[c]);
        g_scale = 0.9f / mm;
    }
}

// ---------------------------------------------------------------------------
// K2b: xg = (xe - centroid)*scale, stored transposed per-graph [g][k][node];
//      sq[node] = sum_k xg^2
// ---------------------------------------------------------------------------
__global__ void __launch_bounds__(256) k_prep(const float* __restrict__ xe) {
    __shared__ float cs[32];
    const int t = threadIdx.x;
    if (t < 32) cs[t] = g_centroid[t];
    __syncthreads();

    const float scale = g_scale;
    const int node = blockIdx.x * 256 + t;
    const int g = node >> 10, local = node & 1023;

    const float4* xr = (const float4*)(xe + (size_t)node * EMB);
    float v[32];
    #pragma unroll
    for (int i = 0; i < 8; i++) {
        float4 q = xr[i];
        v[i * 4 + 0] = q.x; v[i * 4 + 1] = q.y;
        v[i * 4 + 2] = q.z; v[i * 4 + 3] = q.w;
    }
    float sq = 0.f;
    float* basep = g_xgT + (g * EMB) * NPG + local;
    #pragma unroll
    for (int k = 0; k < 32; k++) {
        float vv = (v[k] - cs[k]) * scale;
        sq = fmaf(vv, vv, sq);
        basep[k * NPG] = vv;
    }
    g_sq[node] = sq;
}

// ---------------------------------------------------------------------------
// K3: per graph, D = max(sq_i + sq_j - 2*<xg_i,xg_j>, 0);
//     weight = sigmoid(T*(|thr| - D)); also writes src/dst index streams.
// 128x128 tile per block, 8x8 microtile, contiguous-per-thread columns so
// all stores are STG.128 coalesced.
// ---------------------------------------------------------------------------
__global__ void __launch_bounds__(256) k_main(const float* __restrict__ tptr,
                                              const float* __restrict__ thptr,
                                              float* __restrict__ out) {
    __shared__ __align__(16) float As[32][128];
    __shared__ __align__(16) float Bs[32][128];
    __shared__ float sqa[128], sqb[128];

    const int t = threadIdx.x;          // 256
    const int g = blockIdx.z;
    const int rb = blockIdx.y * 128;
    const int cb = blockIdx.x * 128;
    const float* base = g_xgT + g * (EMB * NPG);

    #pragma unroll
    for (int it = 0; it < 4; it++) {
        int idx = t + it * 256;          // 0..1023 float4 slots
        int k = idx >> 5;
        int m4 = (idx & 31) << 2;
        *(float4*)&As[k][m4] = *(const float4*)&base[k * NPG + rb + m4];
        *(float4*)&Bs[k][m4] = *(const float4*)&base[k * NPG + cb + m4];
    }
    if (t < 128) sqa[t] = g_sq[g * NPG + rb + t];
    else         sqb[t - 128] = g_sq[g * NPG + cb + (t - 128)];
    __syncthreads();

    const int tx = t & 15, ty = t >> 4;   // tx: column group, ty: row group
    float acc[8][8];
    #pragma unroll
    for (int i = 0; i < 8; i++)
        #pragma unroll
        for (int j = 0; j < 8; j++) acc[i][j] = 0.f;

    #pragma unroll 8
    for (int k = 0; k < 32; k++) {
        float a[8], b[8];
        float4 a0 = *(const float4*)&As[k][ty * 8];
        float4 a1 = *(const float4*)&As[k][ty * 8 + 4];
        float4 b0 = *(const float4*)&Bs[k][tx * 8];
        float4 b1 = *(const float4*)&Bs[k][tx * 8 + 4];
        a[0] = a0.x; a[1] = a0.y; a[2] = a0.z; a[3] = a0.w;
        a[4] = a1.x; a[5] = a1.y; a[6] = a1.z; a[7] = a1.w;
        b[0] = b0.x; b[1] = b0.y; b[2] = b0.z; b[3] = b0.w;
        b[4] = b1.x; b[5] = b1.y; b[6] = b1.z; b[7] = b1.w;
        #pragma unroll
        for (int i = 0; i < 8; i++)
            #pragma unroll
            for (int j = 0; j < 8; j++)
                acc[i][j] = fmaf(a[i], b[j], acc[i][j]);
    }

    const float temp = *tptr;
    const float ath = fabsf(*thptr);
    float* wp = out + OFF_W;
    float* sp = out + OFF_SRC;
    float* dp = out + OFF_DST;
    const int gb = g * (NPG * NPG);
    const int cbase = cb + tx * 8;

    #pragma unroll
    for (int i = 0; i < 8; i++) {
        int r = rb + ty * 8 + i;
        int rowoff = gb + r * NPG;
        float sa = sqa[ty * 8 + i];
        float srcv = (float)(g * NPG + r);
        float4 sv = make_float4(srcv, srcv, srcv, srcv);
        #pragma unroll
        for (int jc = 0; jc < 2; jc++) {
            float4 wv, dv;
            float* wq = (float*)&wv;
            float* dq = (float*)&dv;
            #pragma unroll
            for (int q = 0; q < 4; q++) {
                int j = jc * 4 + q;
                int c = cbase + j;
                float D = fmaxf(sa + sqb[tx * 8 + j] - 2.f * acc[i][j], 0.f);
                float z = temp * (ath - D);
                wq[q] = __fdividef(1.f, 1.f + __expf(-z));
                dq[q] = (float)(g * NPG + c);
            }
            int o = rowoff + cbase + jc * 4;
            *(float4*)(wp + o) = wv;
            *(float4*)(sp + o) = sv;
            *(float4*)(dp + o) = dv;
        }
    }
}

// ---------------------------------------------------------------------------
extern "C" void kernel_launch(void* const* d_in, const int* in_sizes, int n_in,
                              void* d_out, int out_size) {
    const float* x    = (const float*)d_in[0];
    const float* W    = (const float*)d_in[1];
    const float* temp = (const float*)d_in[2];
    const float* thr  = (const float*)d_in[3];
    float* out = (float*)d_out;

    k_gemm <<<1024, 256>>>(x, W, out);
    k_stats<<<1, 1024>>>(out);
    k_prep <<<128, 256>>>(out);
    k_main <<<dim3(8, 8, NG), 256>>>(temp, thr, out);
}

// round 2
// speedup vs baseline: 1.2024x; 1.2024x over previous
#include <cuda_runtime.h>

#define NG    32
#define NPG   1024
#define NN    32768
#define FDIM  128
#define EMB   32

// output layout (float32 concat of (xe, edge_index_out, edge_weight))
#define OFF_SRC 1048576
#define OFF_DST 34603008
#define OFF_W   68157440

// scratch (static __device__ globals, no allocation)
__device__ __align__(16) float g_xgT[NG * EMB * NPG];  // [g][k][node] transposed
__device__ float g_sq[NN];
__device__ float g_centroid[EMB];
__device__ float g_scale;

// ---------------------------------------------------------------------------
// packed f32x2 helpers (Blackwell FFMA2 path, PTX-only)
// ---------------------------------------------------------------------------
__device__ __forceinline__ void fma2(unsigned long long& d,
                                     unsigned long long a,
                                     unsigned long long b) {
    asm("fma.rn.f32x2 %0, %1, %2, %0;" : "+l"(d) : "l"(a), "l"(b));
}
__device__ __forceinline__ unsigned long long dup2(float a) {
    unsigned long long r;
    asm("mov.b64 %0, {%1, %1};" : "=l"(r) : "f"(a));
    return r;
}
__device__ __forceinline__ void unpack2(float& lo, float& hi, unsigned long long v) {
    asm("mov.b64 {%0, %1}, %2;" : "=f"(lo), "=f"(hi) : "l"(v));
}

// ---------------------------------------------------------------------------
// K1: xe = x @ W   (32768x128 @ 128x32), writes xe into d_out[0..1048576)
// ---------------------------------------------------------------------------
__global__ void __launch_bounds__(256) k_gemm(const float* __restrict__ x,
                                              const float* __restrict__ W,
                                              float* __restrict__ xe) {
    __shared__ __align__(16) float WsT[32][132];
    __shared__ __align__(16) float xs[32][128];

    const int t = threadIdx.x;
    for (int i = t; i < FDIM * EMB; i += 256) {
        int k = i >> 5, c = i & 31;
        WsT[c][k] = W[i];
    }
    const int warp = t >> 5, lane = t & 31;
    #pragma unroll
    for (int rr = 0; rr < 4; rr++) {
        int lr = warp * 4 + rr;
        int row = blockIdx.x * 32 + lr;
        float4 v = ((const float4*)(x + (size_t)row * FDIM))[lane];
        *(float4*)&xs[lr][lane * 4] = v;
    }
    __syncthreads();

    #pragma unroll
    for (int rr = 0; rr < 4; rr++) {
        int lr = warp * 4 + rr;
        int row = blockIdx.x * 32 + lr;
        const float4* wv4 = (const float4*)&WsT[lane][0];
        const float4* xv4 = (const float4*)&xs[lr][0];
        float acc = 0.f;
        #pragma unroll
        for (int kq = 0; kq < 32; kq++) {
            float4 wv = wv4[kq];
            float4 xv = xv4[kq];
            acc = fmaf(xv.x, wv.x, acc);
            acc = fmaf(xv.y, wv.y, acc);
            acc = fmaf(xv.z, wv.z, acc);
            acc = fmaf(xv.w, wv.w, acc);
        }
        xe[row * EMB + lane] = acc;
    }
}

// ---------------------------------------------------------------------------
// K2: centroid = mean(xe[:1024], axis=0); scale = 0.9/max|xe[:1024]-centroid|
// single block, 1024 threads; one pass over xe, values held in registers
// ---------------------------------------------------------------------------
__global__ void __launch_bounds__(1024) k_stats(const float* __restrict__ xe) {
    __shared__ float ps[32][33];
    __shared__ float cent[32];
    __shared__ float wmax[32];
    const int t = threadIdx.x, lane = t & 31, warp = t >> 5;

    // thread t owns row t: 32 contiguous floats (one 128B line)
    float v[32];
    const float4* xr = (const float4*)(xe + t * EMB);
    #pragma unroll
    for (int i = 0; i < 8; i++) {
        float4 q = xr[i];
        v[i * 4 + 0] = q.x; v[i * 4 + 1] = q.y;
        v[i * 4 + 2] = q.z; v[i * 4 + 3] = q.w;
    }

    // per-column sums: butterfly-reduce each column across the warp
    float mycol = 0.f;
    #pragma unroll
    for (int c = 0; c < 32; c++) {
        float s = v[c];
        #pragma unroll
        for (int off = 16; off > 0; off >>= 1)
            s += __shfl_xor_sync(0xffffffffu, s, off);
        if (c == lane) mycol = s;
    }
    ps[warp][lane] = mycol;
    __syncthreads();
    if (t < 32) {
        float c = 0.f;
        #pragma unroll
        for (int p = 0; p < 32; p++) c += ps[p][t];
        c *= (1.0f / 1024.0f);
        cent[t] = c;
        g_centroid[t] = c;
    }
    __syncthreads();

    // max |v - centroid| (global scalar)
    float m = 0.f;
    #pragma unroll
    for (int c = 0; c < 32; c++) m = fmaxf(m, fabsf(v[c] - cent[c]));
    #pragma unroll
    for (int off = 16; off > 0; off >>= 1)
        m = fmaxf(m, __shfl_xor_sync(0xffffffffu, m, off));
    if (lane == 0) wmax[warp] = m;
    __syncthreads();
    if (t == 0) {
        float mm = 0.f;
        #pragma unroll
        for (int p = 0; p < 32; p++) mm = fmaxf(mm, wmax[p]);
        g_scale = 0.9f / mm;
    }
}

// ---------------------------------------------------------------------------
// K2b: xg = (xe - centroid)*scale, stored transposed per-graph [g][k][node];
//      sq[node] = sum_k xg^2
// ---------------------------------------------------------------------------
__global__ void __launch_bounds__(256) k_prep(const float* __restrict__ xe) {
    __shared__ float cs[32];
    const int t = threadIdx.x;
    if (t < 32) cs[t] = g_centroid[t];
    __syncthreads();

    const float scale = g_scale;
    const int node = blockIdx.x * 256 + t;
    const int g = node >> 10, local = node & 1023;

    const float4* xr = (const float4*)(xe + (size_t)node * EMB);
    float v[32];
    #pragma unroll
    for (int i = 0; i < 8; i++) {
        float4 q = xr[i];
        v[i * 4 + 0] = q.x; v[i * 4 + 1] = q.y;
        v[i * 4 + 2] = q.z; v[i * 4 + 3] = q.w;
    }
    float sq = 0.f;
    float* basep = g_xgT + (g * EMB) * NPG + local;
    #pragma unroll
    for (int k = 0; k < 32; k++) {
        float vv = (v[k] - cs[k]) * scale;
        sq = fmaf(vv, vv, sq);
        basep[k * NPG] = vv;
    }
    g_sq[node] = sq;
}

// ---------------------------------------------------------------------------
// K3: per graph, D = max(sq_i + sq_j - 2*<xg_i,xg_j>, 0);
//     weight = sigmoid(T*(|thr| - D)); src/dst index streams written EARLY
//     (before the mainloop) so they drain during compute. f32x2 packed FMA.
// ---------------------------------------------------------------------------
__global__ void __launch_bounds__(256, 2) k_main(const float* __restrict__ tptr,
                                                 const float* __restrict__ thptr,
                                                 float* __restrict__ out) {
    __shared__ __align__(16) float As[32][128];
    __shared__ __align__(16) float Bs[32][128];
    __shared__ float sqa[128], sqb[128];

    const int t = threadIdx.x;          // 256
    const int g = blockIdx.z;
    const int rb = blockIdx.y * 128;
    const int cb = blockIdx.x * 128;
    const float* base = g_xgT + g * (EMB * NPG);

    // smem fill (issues LDG chains early)
    #pragma unroll
    for (int it = 0; it < 4; it++) {
        int idx = t + it * 256;
        int k = idx >> 5;
        int m4 = (idx & 31) << 2;
        *(float4*)&As[k][m4] = *(const float4*)&base[k * NPG + rb + m4];
        *(float4*)&Bs[k][m4] = *(const float4*)&base[k * NPG + cb + m4];
    }
    if (t < 128) sqa[t] = g_sq[g * NPG + rb + t];
    else         sqb[t - 128] = g_sq[g * NPG + cb + (t - 128)];

    const int tx = t & 15, ty = t >> 4;
    const int gb = g * (NPG * NPG);
    const int cbase = cb + tx * 8;

    // ---- EARLY src/dst stores: independent of the Gram result ----
    {
        float* sp = out + OFF_SRC;
        float* dp = out + OFF_DST;
        float4 dv0, dv1;
        dv0.x = (float)(g * NPG + cbase + 0); dv0.y = (float)(g * NPG + cbase + 1);
        dv0.z = (float)(g * NPG + cbase + 2); dv0.w = (float)(g * NPG + cbase + 3);
        dv1.x = (float)(g * NPG + cbase + 4); dv1.y = (float)(g * NPG + cbase + 5);
        dv1.z = (float)(g * NPG + cbase + 6); dv1.w = (float)(g * NPG + cbase + 7);
        #pragma unroll
        for (int i = 0; i < 8; i++) {
            int r = rb + ty * 8 + i;
            int o = gb + r * NPG + cbase;
            float s = (float)(g * NPG + r);
            float4 sv = make_float4(s, s, s, s);
            __stcs((float4*)(sp + o), sv);
            __stcs((float4*)(sp + o + 4), sv);
            __stcs((float4*)(dp + o), dv0);
            __stcs((float4*)(dp + o + 4), dv1);
        }
    }
    __syncthreads();

    // ---- mainloop: packed f32x2 FMA ----
    unsigned long long acc[8][4];
    #pragma unroll
    for (int i = 0; i < 8; i++)
        #pragma unroll
        for (int jp = 0; jp < 4; jp++) acc[i][jp] = 0ULL;

    #pragma unroll 8
    for (int k = 0; k < 32; k++) {
        float4 a0 = *(const float4*)&As[k][ty * 8];
        float4 a1 = *(const float4*)&As[k][ty * 8 + 4];
        ulonglong2 bq0 = *(const ulonglong2*)&Bs[k][tx * 8];
        ulonglong2 bq1 = *(const ulonglong2*)&Bs[k][tx * 8 + 4];
        unsigned long long bp[4] = {bq0.x, bq0.y, bq1.x, bq1.y};
        unsigned long long ad[8];
        ad[0] = dup2(a0.x); ad[1] = dup2(a0.y);
        ad[2] = dup2(a0.z); ad[3] = dup2(a0.w);
        ad[4] = dup2(a1.x); ad[5] = dup2(a1.y);
        ad[6] = dup2(a1.z); ad[7] = dup2(a1.w);
        #pragma unroll
        for (int i = 0; i < 8; i++)
            #pragma unroll
            for (int jp = 0; jp < 4; jp++)
                fma2(acc[i][jp], ad[i], bp[jp]);
    }

    // ---- epilogue: weights only ----
    const float temp = *tptr;
    const float ath = fabsf(*thptr);
    float* wp = out + OFF_W;

    float sb[8];
    #pragma unroll
    for (int j = 0; j < 8; j++) sb[j] = sqb[tx * 8 + j];

    #pragma unroll
    for (int i = 0; i < 8; i++) {
        int r = rb + ty * 8 + i;
        int rowoff = gb + r * NPG;
        float sa = sqa[ty * 8 + i];
        #pragma unroll
        for (int jc = 0; jc < 2; jc++) {
            float4 wv;
            float* wq = (float*)&wv;
            #pragma unroll
            for (int qp = 0; qp < 2; qp++) {
                int jp = jc * 2 + qp;
                float d0, d1;
                unpack2(d0, d1, acc[i][jp]);
                float D0 = fmaxf(sa + sb[jp * 2 + 0] - 2.f * d0, 0.f);
                float D1 = fmaxf(sa + sb[jp * 2 + 1] - 2.f * d1, 0.f);
                float z0 = temp * (ath - D0);
                float z1 = temp * (ath - D1);
                wq[qp * 2 + 0] = __fdividef(1.f, 1.f + __expf(-z0));
                wq[qp * 2 + 1] = __fdividef(1.f, 1.f + __expf(-z1));
            }
            int o = rowoff + cbase + jc * 4;
            __stcs((float4*)(wp + o), wv);
        }
    }
}

// ---------------------------------------------------------------------------
extern "C" void kernel_launch(void* const* d_in, const int* in_sizes, int n_in,
                              void* d_out, int out_size) {
    const float* x    = (const float*)d_in[0];
    const float* W    = (const float*)d_in[1];
    const float* temp = (const float*)d_in[2];
    const float* thr  = (const float*)d_in[3];
    float* out = (float*)d_out;

    k_gemm <<<1024, 256>>>(x, W, out);
    k_stats<<<1, 1024>>>(out);
    k_prep <<<128, 256>>>(out);
    k_main <<<dim3(8, 8, NG), 256>>>(temp, thr, out);
}

// round 3
// speedup vs baseline: 1.4423x; 1.1995x over previous
#include <cuda_runtime.h>

#define NG    32
#define NPG   1024
#define NN    32768
#define FDIM  128
#define EMB   32

// output layout (float32 concat of (xe, edge_index_out, edge_weight))
#define OFF_SRC 1048576
#define OFF_DST 34603008
#define OFF_W   68157440

__device__ __align__(16) float g_centroid[EMB];
__device__ float g_scale;

// ---------------------------------------------------------------------------
// packed f32x2 helpers (Blackwell FFMA2 path, PTX-only)
// ---------------------------------------------------------------------------
__device__ __forceinline__ void fma2(unsigned long long& d,
                                     unsigned long long a,
                                     unsigned long long b) {
    asm("fma.rn.f32x2 %0, %1, %2, %0;" : "+l"(d) : "l"(a), "l"(b));
}
__device__ __forceinline__ unsigned long long dup2(float a) {
    unsigned long long r;
    asm("mov.b64 %0, {%1, %1};" : "=l"(r) : "f"(a));
    return r;
}
__device__ __forceinline__ void unpack2(float& lo, float& hi, unsigned long long v) {
    asm("mov.b64 {%0, %1}, %2;" : "=f"(lo), "=f"(hi) : "l"(v));
}

// ---------------------------------------------------------------------------
// K1: xe = x @ W   (32768x128 @ 128x32) -> d_out[0..1048576)
// ---------------------------------------------------------------------------
__global__ void __launch_bounds__(256) k_gemm(const float* __restrict__ x,
                                              const float* __restrict__ W,
                                              float* __restrict__ xe) {
    __shared__ __align__(16) float WsT[32][132];
    __shared__ __align__(16) float xs[32][128];

    const int t = threadIdx.x;
    for (int i = t; i < FDIM * EMB; i += 256) {
        int k = i >> 5, c = i & 31;
        WsT[c][k] = W[i];
    }
    const int warp = t >> 5, lane = t & 31;
    #pragma unroll
    for (int rr = 0; rr < 4; rr++) {
        int lr = warp * 4 + rr;
        int row = blockIdx.x * 32 + lr;
        float4 v = ((const float4*)(x + (size_t)row * FDIM))[lane];
        *(float4*)&xs[lr][lane * 4] = v;
    }
    __syncthreads();

    #pragma unroll
    for (int rr = 0; rr < 4; rr++) {
        int lr = warp * 4 + rr;
        int row = blockIdx.x * 32 + lr;
        const float4* wv4 = (const float4*)&WsT[lane][0];
        const float4* xv4 = (const float4*)&xs[lr][0];
        float acc = 0.f;
        #pragma unroll
        for (int kq = 0; kq < 32; kq++) {
            float4 wv = wv4[kq];
            float4 xv = xv4[kq];
            acc = fmaf(xv.x, wv.x, acc);
            acc = fmaf(xv.y, wv.y, acc);
            acc = fmaf(xv.z, wv.z, acc);
            acc = fmaf(xv.w, wv.w, acc);
        }
        xe[row * EMB + lane] = acc;
    }
}

// ---------------------------------------------------------------------------
// K2: centroid = mean(xe[:1024], axis=0); scale = 0.9/max|xe[:1024]-centroid|
// ---------------------------------------------------------------------------
__global__ void __launch_bounds__(1024) k_stats(const float* __restrict__ xe) {
    __shared__ float ps[32][33];
    __shared__ float cent[32];
    __shared__ float wmax[32];
    const int t = threadIdx.x, lane = t & 31, warp = t >> 5;

    float v[32];
    const float4* xr = (const float4*)(xe + t * EMB);
    #pragma unroll
    for (int i = 0; i < 8; i++) {
        float4 q = xr[i];
        v[i * 4 + 0] = q.x; v[i * 4 + 1] = q.y;
        v[i * 4 + 2] = q.z; v[i * 4 + 3] = q.w;
    }

    float mycol = 0.f;
    #pragma unroll
    for (int c = 0; c < 32; c++) {
        float s = v[c];
        #pragma unroll
        for (int off = 16; off > 0; off >>= 1)
            s += __shfl_xor_sync(0xffffffffu, s, off);
        if (c == lane) mycol = s;
    }
    ps[warp][lane] = mycol;
    __syncthreads();
    if (t < 32) {
        float c = 0.f;
        #pragma unroll
        for (int p = 0; p < 32; p++) c += ps[p][t];
        c *= (1.0f / 1024.0f);
        cent[t] = c;
        g_centroid[t] = c;
    }
    __syncthreads();

    float m = 0.f;
    #pragma unroll
    for (int c = 0; c < 32; c++) m = fmaxf(m, fabsf(v[c] - cent[c]));
    #pragma unroll
    for (int off = 16; off > 0; off >>= 1)
        m = fmaxf(m, __shfl_xor_sync(0xffffffffu, m, off));
    if (lane == 0) wmax[warp] = m;
    __syncthreads();
    if (t == 0) {
        float mm = 0.f;
        #pragma unroll
        for (int p = 0; p < 32; p++) mm = fmaxf(mm, wmax[p]);
        g_scale = 0.9f / mm;
    }
}

// ---------------------------------------------------------------------------
// K3 (fused): normalize xe on the fly -> smem (transposed), Gram + sigmoid,
// src/dst stores paced through the k-loop. Tile 64 rows x 128 cols, 256 thr,
// 3 CTAs/SM target.
// ---------------------------------------------------------------------------
__global__ void __launch_bounds__(256, 3) k_main(const float* __restrict__ tptr,
                                                 const float* __restrict__ thptr,
                                                 float* __restrict__ out) {
    __shared__ __align__(16) float As[32][64];    // [k][row]  8KB
    __shared__ __align__(16) float Bs[32][128];   // [k][col] 16KB
    __shared__ float sqa[64], sqb[128];

    const int t = threadIdx.x;          // 256
    const int g = blockIdx.z;
    const int rb = blockIdx.y * 64;
    const int cb = blockIdx.x * 128;
    const float* xe = out;              // xe lives at out[0..)

    // ---- fill: 192 threads each normalize one xe row into one smem column ----
    if (t < 192) {
        const float4* c4 = (const float4*)g_centroid;
        const float scale = g_scale;
        const int row = (t < 64) ? (rb + t) : (cb + (t - 64));
        const float4* xr = (const float4*)(xe + (size_t)(g * NPG + row) * EMB);
        float sq = 0.f;
        #pragma unroll
        for (int i = 0; i < 8; i++) {
            float4 q = __ldg(&xr[i]);
            float4 cv = __ldg(&c4[i]);
            float v0 = (q.x - cv.x) * scale;
            float v1 = (q.y - cv.y) * scale;
            float v2 = (q.z - cv.z) * scale;
            float v3 = (q.w - cv.w) * scale;
            sq = fmaf(v0, v0, fmaf(v1, v1, fmaf(v2, v2, fmaf(v3, v3, sq))));
            int k = i * 4;
            if (t < 64) {
                As[k][t] = v0; As[k + 1][t] = v1;
                As[k + 2][t] = v2; As[k + 3][t] = v3;
            } else {
                int m = t - 64;
                Bs[k][m] = v0; Bs[k + 1][m] = v1;
                Bs[k + 2][m] = v2; Bs[k + 3][m] = v3;
            }
        }
        if (t < 64) sqa[t] = sq; else sqb[t - 64] = sq;
    }
    __syncthreads();

    const int tx = t & 15, ty = t >> 4;
    const int r0 = ty * 4;              // local row base
    const int j0 = tx * 4;              // first col group
    const int j1 = 64 + tx * 4;         // second col group
    const int gb = g * (NPG * NPG);
    const int nodebase = g * NPG;

    unsigned long long acc[4][4];
    #pragma unroll
    for (int i = 0; i < 4; i++)
        #pragma unroll
        for (int jp = 0; jp < 4; jp++) acc[i][jp] = 0ULL;

    float* sp = out + OFF_SRC;
    float* dp = out + OFF_DST;

    #pragma unroll
    for (int kc = 0; kc < 4; kc++) {
        // ---- paced src/dst stores: one output row per k-chunk ----
        {
            int r = rb + r0 + kc;
            int o = gb + r * NPG + cb;
            float s = (float)(nodebase + r);
            float4 sv = make_float4(s, s, s, s);
            float4 dv0, dv1;
            int c0 = nodebase + cb + j0;
            int c1 = nodebase + cb + j1;
            dv0.x = (float)(c0 + 0); dv0.y = (float)(c0 + 1);
            dv0.z = (float)(c0 + 2); dv0.w = (float)(c0 + 3);
            dv1.x = (float)(c1 + 0); dv1.y = (float)(c1 + 1);
            dv1.z = (float)(c1 + 2); dv1.w = (float)(c1 + 3);
            __stcs((float4*)(sp + o + j0), sv);
            __stcs((float4*)(sp + o + j1), sv);
            __stcs((float4*)(dp + o + j0), dv0);
            __stcs((float4*)(dp + o + j1), dv1);
        }
        // ---- 8 k-iterations ----
        #pragma unroll
        for (int kk = 0; kk < 8; kk++) {
            int k = kc * 8 + kk;
            float4 a = *(const float4*)&As[k][r0];
            ulonglong2 b0 = *(const ulonglong2*)&Bs[k][j0];
            ulonglong2 b1 = *(const ulonglong2*)&Bs[k][j1];
            unsigned long long ad0 = dup2(a.x);
            unsigned long long ad1 = dup2(a.y);
            unsigned long long ad2 = dup2(a.z);
            unsigned long long ad3 = dup2(a.w);
            fma2(acc[0][0], ad0, b0.x); fma2(acc[0][1], ad0, b0.y);
            fma2(acc[0][2], ad0, b1.x); fma2(acc[0][3], ad0, b1.y);
            fma2(acc[1][0], ad1, b0.x); fma2(acc[1][1], ad1, b0.y);
            fma2(acc[1][2], ad1, b1.x); fma2(acc[1][3], ad1, b1.y);
            fma2(acc[2][0], ad2, b0.x); fma2(acc[2][1], ad2, b0.y);
            fma2(acc[2][2], ad2, b1.x); fma2(acc[2][3], ad2, b1.y);
            fma2(acc[3][0], ad3, b0.x); fma2(acc[3][1], ad3, b0.y);
            fma2(acc[3][2], ad3, b1.x); fma2(acc[3][3], ad3, b1.y);
        }
    }

    // ---- epilogue: weights ----
    const float temp = *tptr;
    const float ath = fabsf(*thptr);
    float* wp = out + OFF_W;
    float4 sb0 = *(const float4*)&sqb[j0];
    float4 sb1 = *(const float4*)&sqb[j1];
    float sb[8] = {sb0.x, sb0.y, sb0.z, sb0.w, sb1.x, sb1.y, sb1.z, sb1.w};

    #pragma unroll
    for (int i = 0; i < 4; i++) {
        int r = rb + r0 + i;
        int o = gb + r * NPG + cb;
        float sa = sqa[r0 + i];
        float4 w0, w1;
        float* wq0 = (float*)&w0;
        float* wq1 = (float*)&w1;
        #pragma unroll
        for (int jp = 0; jp < 2; jp++) {
            float d0, d1;
            unpack2(d0, d1, acc[i][jp]);
            float D0 = fmaxf(sa + sb[jp * 2 + 0] - 2.f * d0, 0.f);
            float D1 = fmaxf(sa + sb[jp * 2 + 1] - 2.f * d1, 0.f);
            wq0[jp * 2 + 0] = __fdividef(1.f, 1.f + __expf(-temp * (ath - D0)));
            wq0[jp * 2 + 1] = __fdividef(1.f, 1.f + __expf(-temp * (ath - D1)));
        }
        #pragma unroll
        for (int jp = 0; jp < 2; jp++) {
            float d0, d1;
            unpack2(d0, d1, acc[i][jp + 2]);
            float D0 = fmaxf(sa + sb[4 + jp * 2 + 0] - 2.f * d0, 0.f);
            float D1 = fmaxf(sa + sb[4 + jp * 2 + 1] - 2.f * d1, 0.f);
            wq1[jp * 2 + 0] = __fdividef(1.f, 1.f + __expf(-temp * (ath - D0)));
            wq1[jp * 2 + 1] = __fdividef(1.f, 1.f + __expf(-temp * (ath - D1)));
        }
        __stcs((float4*)(wp + o + j0), w0);
        __stcs((float4*)(wp + o + j1), w1);
    }
}

// ---------------------------------------------------------------------------
extern "C" void kernel_launch(void* const* d_in, const int* in_sizes, int n_in,
                              void* d_out, int out_size) {
    const float* x    = (const float*)d_in[0];
    const float* W    = (const float*)d_in[1];
    const float* temp = (const float*)d_in[2];
    const float* thr  = (const float*)d_in[3];
    float* out = (float*)d_out;

    k_gemm <<<1024, 256>>>(x, W, out);
    k_stats<<<1, 1024>>>(out);
    k_main <<<dim3(8, 16, NG), 256>>>(temp, thr, out);
}